// round 9
// baseline (speedup 1.0000x reference)
#include <cuda_runtime.h>
#include <cuda_fp16.h>
#include <cuda_bf16.h>

// GuidedFilter (4,3,1024,1024) fp32, R=40, eps=1e-3.
// R8 design (SEG=16, half2 a,b intermediate, 1 barrier/row double-buffered)
// with vectorized shared-prefix machinery:
//  - prefix stored per 128-col chunk at slot==count (0..128), chunk stride 132
//  - STS.128 stores via shuffle-realign (lane l stores counts 4l..4l+3)
//  - interior gathers: lo = 1 LDS.128, hi = 2 LDS.128 + select, T = 1 LDS.32
//    (slot 131 of each chunk is a zero sentinel for the same-chunk case)
//  - edge threads (tid<=9, tid>=246) use scalar fallback

#define HH   1024
#define WW   1024
#define NIMG 12
#define RAD  40
#define SEG  16
#define NTH  256
#define CS2  132
#define ESZ  (8 * CS2)

#define EPS 1e-3f

struct __align__(16) H2x4 { __half2 v[4]; };

__device__ H2x4 g_ab[(size_t)NIMG * HH * 256];

#define WSCAN(val)                                                    \
    {                                                                 \
        _Pragma("unroll")                                             \
        for (int o = 1; o < 32; o <<= 1) {                            \
            float _n = __shfl_up_sync(0xffffffffu, (val), o);         \
            if (lane >= o) (val) += _n;                               \
        }                                                             \
    }

// local prefix + warp scan + aligned STS.128 (lane l -> counts 4l..4l+3),
// lane 31 stores chunk total (count 128) at slot 128.
#define SCAN_STORE_V(s0, s1, s2, s3, E)                               \
    {                                                                 \
        float q0 = (s0);                                              \
        float q1 = q0 + (s1);                                         \
        float q2 = q1 + (s2);                                         \
        float q3 = q2 + (s3);                                         \
        float inc = q3;                                               \
        WSCAN(inc);                                                   \
        float x = inc - q3;                                           \
        float prev = __shfl_up_sync(0xffffffffu, inc, 1);             \
        if (lane == 0) prev = 0.f;                                    \
        float4 st = make_float4(prev, x + q0, x + q1, x + q2);        \
        *(float4*)((E) + eb + 4 * lane) = st;                         \
        if (lane == 31) (E)[eb + 128] = inc;                          \
    }

struct GatherIdx {
    int idxL, idxH, idxT;        // interior fast path
    int lI[4], hI[4], tI[4];     // edge fallback
    float cntx[4];
    bool edge;
};

static __device__ __forceinline__ void make_gidx(GatherIdx& g, int c0) {
    g.edge = (c0 < RAD) || (c0 + 3 + RAD > WW - 1);
#pragma unroll
    for (int j = 0; j < 4; ++j) {
        int c  = c0 + j;
        int lo = max(c - RAD, 0);
        int hi = min(c + RAD, WW - 1);
        int ca = lo >> 7;
        int cb = hi >> 7;
        g.lI[j] = ca * CS2 + (lo - 128 * ca);
        g.hI[j] = cb * CS2 + (hi + 1 - 128 * cb);
        g.tI[j] = ca * CS2 + ((cb > ca) ? 128 : 131);
        g.cntx[j] = (float)(hi - lo + 1);
    }
    int lo0 = c0 - RAD;        // valid for interior threads
    int hi0 = c0 + RAD;
    int ca = lo0 >> 7;
    int cb = hi0 >> 7;
    g.idxL = ca * CS2 + (lo0 & 127);
    g.idxH = cb * CS2 + (hi0 & 127);       // slot kh-1 (aligned)
    g.idxT = ca * CS2 + ((cb > ca) ? 128 : 131);
}

static __device__ __forceinline__ float4 gather_win(const float* __restrict__ E,
                                                    const GatherIdx& g) {
    float4 u;
    if (!g.edge) {
        float4 L = *(const float4*)(E + g.idxL);
        float4 A = *(const float4*)(E + g.idxH);
        float4 B = *(const float4*)(E + g.idxH + 4);
        float T = E[g.idxT];
        u.x = A.y - L.x + T;
        u.y = A.z - L.y + T;
        u.z = A.w - L.z + T;
        u.w = B.x - L.w + T;
    } else {
        u.x = E[g.hI[0]] - E[g.lI[0]] + E[g.tI[0]];
        u.y = E[g.hI[1]] - E[g.lI[1]] + E[g.tI[1]];
        u.z = E[g.hI[2]] - E[g.lI[2]] + E[g.tI[2]];
        u.w = E[g.hI[3]] - E[g.lI[3]] + E[g.tI[3]];
    }
    return u;
}

// ---------------------------------------------------------------------------
// Stage 1: I,p -> box means of {I,p,Ip,II} -> a,b (half2)
// ---------------------------------------------------------------------------
__global__ __launch_bounds__(NTH) void k_stage1(const float* __restrict__ I,
                                                const float* __restrict__ P) {
    __shared__ float sE[2][4][ESZ];

    const int tid  = threadIdx.x;
    const int lane = tid & 31;
    const int w    = tid >> 5;
    const int img  = blockIdx.y;
    const int y0   = blockIdx.x * SEG;
    const size_t b4 = (size_t)img * HH * 256;

    const float4* __restrict__ I4 = (const float4*)I + b4;
    const float4* __restrict__ P4 = (const float4*)P + b4;
    H2x4* __restrict__ AB = g_ab + b4;

    const int eb = w * CS2;

    GatherIdx g;
    make_gidx(g, tid * 4);

    // zero sentinels (slot 131 of each chunk, both buffers, all fields)
    if (tid < 8) {
#pragma unroll
        for (int b = 0; b < 2; ++b)
#pragma unroll
            for (int f = 0; f < 4; ++f)
                sE[b][f][tid * CS2 + 131] = 0.f;
    }

    float4 rI = make_float4(0, 0, 0, 0);
    float4 rP = rI, rIp = rI, rII = rI;

    const int ys = max(0, y0 - RAD);
    const int ye = min(HH, y0 + RAD);            // exclusive
#pragma unroll 4
    for (int yy = ys; yy < ye; ++yy) {
        float4 i4 = I4[(size_t)yy * 256 + tid];
        float4 p4 = P4[(size_t)yy * 256 + tid];
        rI.x  += i4.x;        rI.y  += i4.y;        rI.z  += i4.z;        rI.w  += i4.w;
        rP.x  += p4.x;        rP.y  += p4.y;        rP.z  += p4.z;        rP.w  += p4.w;
        rIp.x += i4.x * p4.x; rIp.y += i4.y * p4.y; rIp.z += i4.z * p4.z; rIp.w += i4.w * p4.w;
        rII.x += i4.x * i4.x; rII.y += i4.y * i4.y; rII.z += i4.z * i4.z; rII.w += i4.w * i4.w;
    }

    for (int y = y0; y < y0 + SEG; ++y) {
        int ya = y + RAD;
        if (ya < HH) {
            float4 i4 = I4[(size_t)ya * 256 + tid];
            float4 p4 = P4[(size_t)ya * 256 + tid];
            rI.x  += i4.x;        rI.y  += i4.y;        rI.z  += i4.z;        rI.w  += i4.w;
            rP.x  += p4.x;        rP.y  += p4.y;        rP.z  += p4.z;        rP.w  += p4.w;
            rIp.x += i4.x * p4.x; rIp.y += i4.y * p4.y; rIp.z += i4.z * p4.z; rIp.w += i4.w * p4.w;
            rII.x += i4.x * i4.x; rII.y += i4.y * i4.y; rII.z += i4.z * i4.z; rII.w += i4.w * i4.w;
        }

        const int buf = y & 1;
        float* __restrict__ E0 = sE[buf][0];
        float* __restrict__ E1 = sE[buf][1];
        float* __restrict__ E2 = sE[buf][2];
        float* __restrict__ E3 = sE[buf][3];

        SCAN_STORE_V(rI.x,  rI.y,  rI.z,  rI.w,  E0);
        SCAN_STORE_V(rP.x,  rP.y,  rP.z,  rP.w,  E1);
        SCAN_STORE_V(rIp.x, rIp.y, rIp.z, rIp.w, E2);
        SCAN_STORE_V(rII.x, rII.y, rII.z, rII.w, E3);

        __syncthreads();

        float cnty = (float)(min(y + RAD + 1, HH) - max(y - RAD, 0));
        float4 u0 = gather_win(E0, g);
        float4 u1 = gather_win(E1, g);
        float4 u2 = gather_win(E2, g);
        float4 u3 = gather_win(E3, g);

        const float* p0 = &u0.x;
        const float* p1 = &u1.x;
        const float* p2 = &u2.x;
        const float* p3 = &u3.x;
        H2x4 hv;
#pragma unroll
        for (int j = 0; j < 4; ++j) {
            float inv = __fdividef(1.0f, g.cntx[j] * cnty);
            float mI  = p0[j] * inv;
            float mP  = p1[j] * inv;
            float mIp = p2[j] * inv;
            float mII = p3[j] * inv;
            float a = __fdividef(mIp - mI * mP, (mII - mI * mI) + EPS);
            float b = mP - a * mI;
            hv.v[j] = __floats2half2_rn(a, b);
        }
        AB[(size_t)y * 256 + tid] = hv;

        int yr = y - RAD;
        if (yr >= 0) {
            float4 i4 = I4[(size_t)yr * 256 + tid];
            float4 p4 = P4[(size_t)yr * 256 + tid];
            rI.x  -= i4.x;        rI.y  -= i4.y;        rI.z  -= i4.z;        rI.w  -= i4.w;
            rP.x  -= p4.x;        rP.y  -= p4.y;        rP.z  -= p4.z;        rP.w  -= p4.w;
            rIp.x -= i4.x * p4.x; rIp.y -= i4.y * p4.y; rIp.z -= i4.z * p4.z; rIp.w -= i4.w * p4.w;
            rII.x -= i4.x * i4.x; rII.y -= i4.y * i4.y; rII.z -= i4.z * i4.z; rII.w -= i4.w * i4.w;
        }
    }
}

// ---------------------------------------------------------------------------
// Stage 2: a,b (half2) -> box means -> out = mean_a * I + mean_b
// ---------------------------------------------------------------------------
__global__ __launch_bounds__(NTH) void k_stage2(const float* __restrict__ I,
                                                float* __restrict__ out) {
    __shared__ float sE[2][2][ESZ];

    const int tid  = threadIdx.x;
    const int lane = tid & 31;
    const int w    = tid >> 5;
    const int img  = blockIdx.y;
    const int y0   = blockIdx.x * SEG;
    const size_t b4 = (size_t)img * HH * 256;

    const H2x4* __restrict__ AB = g_ab + b4;
    const float4* __restrict__ I4 = (const float4*)I + b4;
    float4* __restrict__ O4 = (float4*)out + b4;

    const int eb = w * CS2;

    GatherIdx g;
    make_gidx(g, tid * 4);

    if (tid < 8) {
#pragma unroll
        for (int b = 0; b < 2; ++b)
#pragma unroll
            for (int f = 0; f < 2; ++f)
                sE[b][f][tid * CS2 + 131] = 0.f;
    }

    float rA[4] = {0.f, 0.f, 0.f, 0.f};
    float rB[4] = {0.f, 0.f, 0.f, 0.f};

    const int ys = max(0, y0 - RAD);
    const int ye = min(HH, y0 + RAD);
#pragma unroll 4
    for (int yy = ys; yy < ye; ++yy) {
        H2x4 h = AB[(size_t)yy * 256 + tid];
#pragma unroll
        for (int j = 0; j < 4; ++j) {
            float2 f = __half22float2(h.v[j]);
            rA[j] += f.x;
            rB[j] += f.y;
        }
    }

    for (int y = y0; y < y0 + SEG; ++y) {
        int ya = y + RAD;
        if (ya < HH) {
            H2x4 h = AB[(size_t)ya * 256 + tid];
#pragma unroll
            for (int j = 0; j < 4; ++j) {
                float2 f = __half22float2(h.v[j]);
                rA[j] += f.x;
                rB[j] += f.y;
            }
        }

        const int buf = y & 1;
        float* __restrict__ E0 = sE[buf][0];
        float* __restrict__ E1 = sE[buf][1];

        SCAN_STORE_V(rA[0], rA[1], rA[2], rA[3], E0);
        SCAN_STORE_V(rB[0], rB[1], rB[2], rB[3], E1);

        __syncthreads();

        float cnty = (float)(min(y + RAD + 1, HH) - max(y - RAD, 0));
        float4 ua = gather_win(E0, g);
        float4 ub = gather_win(E1, g);

        float4 i4 = I4[(size_t)y * 256 + tid];
        const float* ip = &i4.x;
        const float* pa = &ua.x;
        const float* pb = &ub.x;
        float4 ov;
        float* op = &ov.x;
#pragma unroll
        for (int j = 0; j < 4; ++j) {
            float inv = __fdividef(1.0f, g.cntx[j] * cnty);
            op[j] = (pa[j] * inv) * ip[j] + (pb[j] * inv);
        }
        O4[(size_t)y * 256 + tid] = ov;

        int yr = y - RAD;
        if (yr >= 0) {
            H2x4 h = AB[(size_t)yr * 256 + tid];
#pragma unroll
            for (int j = 0; j < 4; ++j) {
                float2 f = __half22float2(h.v[j]);
                rA[j] -= f.x;
                rB[j] -= f.y;
            }
        }
    }
}

extern "C" void kernel_launch(void* const* d_in, const int* in_sizes, int n_in,
                              void* d_out, int out_size) {
    const float* I = (const float*)d_in[0];
    const float* P = (const float*)d_in[1];
    float* out = (float*)d_out;

    dim3 g(HH / SEG, NIMG);
    k_stage1<<<g, NTH>>>(I, P);
    k_stage2<<<g, NTH>>>(I, out);
}

// round 13
// speedup vs baseline: 1.0028x; 1.0028x over previous
#include <cuda_runtime.h>
#include <cuda_fp16.h>
#include <cuda_bf16.h>

// GuidedFilter (4,3,1024,1024) fp32, R=40, eps=1e-3.
// R8 design (SEG=16, half2 a,b, 1 barrier/row, double buffer) + universal
// vectorized prefix machinery:
//  - per-field prefix array: [48-slot zero pad][8 chunks x stride 132][tail]
//  - left window clamp handled by zero pad (negative counts read 0)
//  - right window clamp handled by replicating chunk-7 total into slots 128..171
//  - gather: 3x LDS.128 + 1x LDS.32 per field, no edge branches
//  - store: shuffle-realigned STS.128 per field

#define HH   1024
#define WW   1024
#define NIMG 12
#define RAD  40
#define SEG  16
#define NTH  256
#define PAD  48
#define CS2  132
#define FSZ  (PAD + 7 * CS2 + 172)   // 1144

#define EPS 1e-3f

struct __align__(16) H2x4 { __half2 v[4]; };

__device__ H2x4 g_ab[(size_t)NIMG * HH * 256];

#define WSCAN(val)                                                    \
    {                                                                 \
        _Pragma("unroll")                                             \
        for (int o = 1; o < 32; o <<= 1) {                            \
            float _n = __shfl_up_sync(0xffffffffu, (val), o);         \
            if (lane >= o) (val) += _n;                               \
        }                                                             \
    }

// local prefix + warp scan + aligned STS.128 (lane l -> counts 4l..4l+3).
// chunk totals: chunks 0-6 lane31 scalar at slot 128; chunk 7 replicates its
// total into slots 128..171 (lanes 0..10, one STS.128 each).
#define SCAN_STORE_V(s0, s1, s2, s3, E)                               \
    {                                                                 \
        float q0 = (s0);                                              \
        float q1 = q0 + (s1);                                         \
        float q2 = q1 + (s2);                                         \
        float q3 = q2 + (s3);                                         \
        float inc = q3;                                               \
        WSCAN(inc);                                                   \
        float x = inc - q3;                                           \
        float prev = __shfl_up_sync(0xffffffffu, inc, 1);             \
        if (lane == 0) prev = 0.f;                                    \
        *(float4*)((E) + sbase) = make_float4(prev, x + q0, x + q1, x + q2); \
        if (w == 7) {                                                 \
            float tot = __shfl_sync(0xffffffffu, inc, 31);            \
            if (lane < 11)                                            \
                *(float4*)((E) + PAD + 7 * CS2 + 128 + 4 * lane) =    \
                    make_float4(tot, tot, tot, tot);                  \
        } else if (lane == 31) {                                      \
            (E)[PAD + w * CS2 + 128] = inc;                           \
        }                                                             \
    }

#define GATHER(u, E)                                                  \
    {                                                                 \
        float4 Lv = *(const float4*)((E) + idxL);                     \
        float4 Av = *(const float4*)((E) + idxH);                     \
        float4 Bv = *(const float4*)((E) + idxH + 4);                 \
        float Tv = (E)[idxT];                                         \
        u.x = Av.y - Lv.x + Tv;                                       \
        u.y = Av.z - Lv.y + Tv;                                       \
        u.z = Av.w - Lv.z + Tv;                                       \
        u.w = Bv.x - Lv.w + Tv;                                       \
    }

// ---------------------------------------------------------------------------
// Stage 1: I,p -> box means of {I,p,Ip,II} -> a,b (half2)
// ---------------------------------------------------------------------------
__global__ __launch_bounds__(NTH, 4) void k_stage1(const float* __restrict__ I,
                                                   const float* __restrict__ P) {
    __shared__ float sE[2][4][FSZ];

    const int tid  = threadIdx.x;
    const int lane = tid & 31;
    const int w    = tid >> 5;
    const int img  = blockIdx.y;
    const int y0   = blockIdx.x * SEG;
    const size_t b4 = (size_t)img * HH * 256;

    const float4* __restrict__ I4 = (const float4*)I + b4;
    const float4* __restrict__ P4 = (const float4*)P + b4;
    H2x4* __restrict__ AB = g_ab + b4;

    const int sbase = PAD + w * CS2 + 4 * lane;

    // universal gather indices
    const int c0  = tid * 4;
    const int lo0 = c0 - RAD;
    const int hi0 = c0 + RAD;
    const int idxL = (lo0 < 0) ? (PAD + lo0) : (PAD + (lo0 >> 7) * CS2 + (lo0 & 127));
    const int cbp  = min(hi0 >> 7, 7);
    const int idxH = PAD + cbp * CS2 + (hi0 - 128 * cbp);
    const int caT  = (lo0 < 0) ? 0 : (lo0 >> 7);
    const int idxT = (cbp > caT) ? (PAD + caT * CS2 + 128) : 0;

    float cntx[4];
#pragma unroll
    for (int j = 0; j < 4; ++j) {
        int c = c0 + j;
        cntx[j] = (float)(min(c + RAD, WW - 1) - max(c - RAD, 0) + 1);
    }

    // zero pads (slot 0..PAD-1 of every field/buffer; slot 0 is the T sentinel)
    if (tid < PAD) {
#pragma unroll
        for (int b = 0; b < 2; ++b)
#pragma unroll
            for (int f = 0; f < 4; ++f)
                sE[b][f][tid] = 0.f;
    }

    float4 rI = make_float4(0, 0, 0, 0);
    float4 rP = rI, rIp = rI, rII = rI;

    const int ys = max(0, y0 - RAD);
    const int ye = min(HH, y0 + RAD);            // exclusive
#pragma unroll 4
    for (int yy = ys; yy < ye; ++yy) {
        float4 i4 = I4[(size_t)yy * 256 + tid];
        float4 p4 = P4[(size_t)yy * 256 + tid];
        rI.x  += i4.x;        rI.y  += i4.y;        rI.z  += i4.z;        rI.w  += i4.w;
        rP.x  += p4.x;        rP.y  += p4.y;        rP.z  += p4.z;        rP.w  += p4.w;
        rIp.x += i4.x * p4.x; rIp.y += i4.y * p4.y; rIp.z += i4.z * p4.z; rIp.w += i4.w * p4.w;
        rII.x += i4.x * i4.x; rII.y += i4.y * i4.y; rII.z += i4.z * i4.z; rII.w += i4.w * i4.w;
    }

    for (int y = y0; y < y0 + SEG; ++y) {
        int ya = y + RAD;
        if (ya < HH) {
            float4 i4 = I4[(size_t)ya * 256 + tid];
            float4 p4 = P4[(size_t)ya * 256 + tid];
            rI.x  += i4.x;        rI.y  += i4.y;        rI.z  += i4.z;        rI.w  += i4.w;
            rP.x  += p4.x;        rP.y  += p4.y;        rP.z  += p4.z;        rP.w  += p4.w;
            rIp.x += i4.x * p4.x; rIp.y += i4.y * p4.y; rIp.z += i4.z * p4.z; rIp.w += i4.w * p4.w;
            rII.x += i4.x * i4.x; rII.y += i4.y * i4.y; rII.z += i4.z * i4.z; rII.w += i4.w * i4.w;
        }

        const int buf = y & 1;
        float* __restrict__ E0 = sE[buf][0];
        float* __restrict__ E1 = sE[buf][1];
        float* __restrict__ E2 = sE[buf][2];
        float* __restrict__ E3 = sE[buf][3];

        SCAN_STORE_V(rI.x,  rI.y,  rI.z,  rI.w,  E0);
        SCAN_STORE_V(rP.x,  rP.y,  rP.z,  rP.w,  E1);
        SCAN_STORE_V(rIp.x, rIp.y, rIp.z, rIp.w, E2);
        SCAN_STORE_V(rII.x, rII.y, rII.z, rII.w, E3);

        __syncthreads();

        float cnty = (float)(min(y + RAD + 1, HH) - max(y - RAD, 0));
        float4 u0, u1, u2, u3;
        GATHER(u0, E0);
        GATHER(u1, E1);
        GATHER(u2, E2);
        GATHER(u3, E3);

        const float* p0 = &u0.x;
        const float* p1 = &u1.x;
        const float* p2 = &u2.x;
        const float* p3 = &u3.x;
        H2x4 hv;
#pragma unroll
        for (int j = 0; j < 4; ++j) {
            float inv = __fdividef(1.0f, cntx[j] * cnty);
            float mI  = p0[j] * inv;
            float mP  = p1[j] * inv;
            float mIp = p2[j] * inv;
            float mII = p3[j] * inv;
            float a = __fdividef(mIp - mI * mP, (mII - mI * mI) + EPS);
            float b = mP - a * mI;
            hv.v[j] = __floats2half2_rn(a, b);
        }
        AB[(size_t)y * 256 + tid] = hv;

        int yr = y - RAD;
        if (yr >= 0) {
            float4 i4 = I4[(size_t)yr * 256 + tid];
            float4 p4 = P4[(size_t)yr * 256 + tid];
            rI.x  -= i4.x;        rI.y  -= i4.y;        rI.z  -= i4.z;        rI.w  -= i4.w;
            rP.x  -= p4.x;        rP.y  -= p4.y;        rP.z  -= p4.z;        rP.w  -= p4.w;
            rIp.x -= i4.x * p4.x; rIp.y -= i4.y * p4.y; rIp.z -= i4.z * p4.z; rIp.w -= i4.w * p4.w;
            rII.x -= i4.x * i4.x; rII.y -= i4.y * i4.y; rII.z -= i4.z * i4.z; rII.w -= i4.w * i4.w;
        }
    }
}

// ---------------------------------------------------------------------------
// Stage 2: a,b (half2) -> box means -> out = mean_a * I + mean_b
// ---------------------------------------------------------------------------
__global__ __launch_bounds__(NTH, 5) void k_stage2(const float* __restrict__ I,
                                                   float* __restrict__ out) {
    __shared__ float sE[2][2][FSZ];

    const int tid  = threadIdx.x;
    const int lane = tid & 31;
    const int w    = tid >> 5;
    const int img  = blockIdx.y;
    const int y0   = blockIdx.x * SEG;
    const size_t b4 = (size_t)img * HH * 256;

    const H2x4* __restrict__ AB = g_ab + b4;
    const float4* __restrict__ I4 = (const float4*)I + b4;
    float4* __restrict__ O4 = (float4*)out + b4;

    const int sbase = PAD + w * CS2 + 4 * lane;

    const int c0  = tid * 4;
    const int lo0 = c0 - RAD;
    const int hi0 = c0 + RAD;
    const int idxL = (lo0 < 0) ? (PAD + lo0) : (PAD + (lo0 >> 7) * CS2 + (lo0 & 127));
    const int cbp  = min(hi0 >> 7, 7);
    const int idxH = PAD + cbp * CS2 + (hi0 - 128 * cbp);
    const int caT  = (lo0 < 0) ? 0 : (lo0 >> 7);
    const int idxT = (cbp > caT) ? (PAD + caT * CS2 + 128) : 0;

    float cntx[4];
#pragma unroll
    for (int j = 0; j < 4; ++j) {
        int c = c0 + j;
        cntx[j] = (float)(min(c + RAD, WW - 1) - max(c - RAD, 0) + 1);
    }

    if (tid < PAD) {
#pragma unroll
        for (int b = 0; b < 2; ++b)
#pragma unroll
            for (int f = 0; f < 2; ++f)
                sE[b][f][tid] = 0.f;
    }

    float rA[4] = {0.f, 0.f, 0.f, 0.f};
    float rB[4] = {0.f, 0.f, 0.f, 0.f};

    const int ys = max(0, y0 - RAD);
    const int ye = min(HH, y0 + RAD);
#pragma unroll 4
    for (int yy = ys; yy < ye; ++yy) {
        H2x4 h = AB[(size_t)yy * 256 + tid];
#pragma unroll
        for (int j = 0; j < 4; ++j) {
            float2 f = __half22float2(h.v[j]);
            rA[j] += f.x;
            rB[j] += f.y;
        }
    }

    for (int y = y0; y < y0 + SEG; ++y) {
        int ya = y + RAD;
        if (ya < HH) {
            H2x4 h = AB[(size_t)ya * 256 + tid];
#pragma unroll
            for (int j = 0; j < 4; ++j) {
                float2 f = __half22float2(h.v[j]);
                rA[j] += f.x;
                rB[j] += f.y;
            }
        }

        const int buf = y & 1;
        float* __restrict__ E0 = sE[buf][0];
        float* __restrict__ E1 = sE[buf][1];

        SCAN_STORE_V(rA[0], rA[1], rA[2], rA[3], E0);
        SCAN_STORE_V(rB[0], rB[1], rB[2], rB[3], E1);

        __syncthreads();

        float cnty = (float)(min(y + RAD + 1, HH) - max(y - RAD, 0));
        float4 ua, ub;
        GATHER(ua, E0);
        GATHER(ub, E1);

        float4 i4 = I4[(size_t)y * 256 + tid];
        const float* ip = &i4.x;
        const float* pa = &ua.x;
        const float* pb = &ub.x;
        float4 ov;
        float* op = &ov.x;
#pragma unroll
        for (int j = 0; j < 4; ++j) {
            float inv = __fdividef(1.0f, cntx[j] * cnty);
            op[j] = (pa[j] * inv) * ip[j] + (pb[j] * inv);
        }
        O4[(size_t)y * 256 + tid] = ov;

        int yr = y - RAD;
        if (yr >= 0) {
            H2x4 h = AB[(size_t)yr * 256 + tid];
#pragma unroll
            for (int j = 0; j < 4; ++j) {
                float2 f = __half22float2(h.v[j]);
                rA[j] -= f.x;
                rB[j] -= f.y;
            }
        }
    }
}

extern "C" void kernel_launch(void* const* d_in, const int* in_sizes, int n_in,
                              void* d_out, int out_size) {
    const float* I = (const float*)d_in[0];
    const float* P = (const float*)d_in[1];
    float* out = (float*)d_out;

    dim3 g(HH / SEG, NIMG);
    k_stage1<<<g, NTH>>>(I, P);
    k_stage2<<<g, NTH>>>(I, out);
}

// round 14
// speedup vs baseline: 1.0367x; 1.0338x over previous
#include <cuda_runtime.h>
#include <cuda_fp16.h>
#include <cuda_bf16.h>

// GuidedFilter (4,3,1024,1024) fp32, R=40, eps=1e-3.
// R8 design (best so far: SEG=16, half2 a,b intermediate, 8 warps x 128-col
// chunks, window <= 2 chunks, scalar scan stores + 3 scalar LDS/field/px,
// ONE barrier per row, double-buffered prefixes) + MUFU reduction:
// 1/(cntx*cnty) = invx[j] (per-thread const) * invy (one RCP per row)
// instead of one MUFU.RCP per pixel.

#define HH   1024
#define WW   1024
#define NIMG 12
#define RAD  40
#define SEG  16
#define NTH  256
#define CS   136               // padded chunk stride (PID(128)=132)
#define PID(k) ((k) + ((k) >> 5))
#define ESZ  (8 * CS)          // per field per buffer

#define EPS 1e-3f

struct __align__(16) H2x4 { __half2 v[4]; };

__device__ H2x4 g_ab[(size_t)NIMG * HH * 256];   // (a,b) per pixel, 4 px/entry

#define WSCAN(val)                                                    \
    {                                                                 \
        _Pragma("unroll")                                             \
        for (int o = 1; o < 32; o <<= 1) {                            \
            float _n = __shfl_up_sync(0xffffffffu, (val), o);         \
            if (lane >= o) (val) += _n;                               \
        }                                                             \
    }

// ---------------------------------------------------------------------------
// Stage 1: I,p -> box means of {I,p,Ip,II} -> a,b (half2)
// ---------------------------------------------------------------------------
__global__ __launch_bounds__(NTH) void k_stage1(const float* __restrict__ I,
                                                const float* __restrict__ P) {
    __shared__ float sE[2][4][ESZ];

    const int tid  = threadIdx.x;
    const int lane = tid & 31;
    const int w    = tid >> 5;
    const int img  = blockIdx.y;
    const int y0   = blockIdx.x * SEG;
    const size_t b4 = (size_t)img * HH * 256;

    const float4* __restrict__ I4 = (const float4*)I + b4;
    const float4* __restrict__ P4 = (const float4*)P + b4;
    H2x4* __restrict__ AB = g_ab + b4;

    const int c0 = tid * 4;

    int aLo[4], aHi[4], aT[4];
    float invx[4];
#pragma unroll
    for (int j = 0; j < 4; ++j) {
        int c   = c0 + j;
        int lo  = max(c - RAD, 0);
        int hi1 = min(c + RAD, WW - 1);          // inclusive
        int ca  = lo >> 7;
        int cb  = hi1 >> 7;
        aLo[j]  = ca * CS + PID(lo & 127);
        aHi[j]  = cb * CS + PID((hi1 & 127) + 1);
        aT[j]   = ca * CS + ((cb > ca) ? PID(128) : 0);   // slot 0 of chunk == 0
        invx[j] = 1.0f / (float)(hi1 + 1 - lo);           // init-time full div
    }

    float4 rI = make_float4(0, 0, 0, 0);
    float4 rP = rI, rIp = rI, rII = rI;

    const int ys = max(0, y0 - RAD);
    const int ye = min(HH, y0 + RAD);            // exclusive
#pragma unroll 4
    for (int yy = ys; yy < ye; ++yy) {
        float4 i4 = I4[(size_t)yy * 256 + tid];
        float4 p4 = P4[(size_t)yy * 256 + tid];
        rI.x  += i4.x;        rI.y  += i4.y;        rI.z  += i4.z;        rI.w  += i4.w;
        rP.x  += p4.x;        rP.y  += p4.y;        rP.z  += p4.z;        rP.w  += p4.w;
        rIp.x += i4.x * p4.x; rIp.y += i4.y * p4.y; rIp.z += i4.z * p4.z; rIp.w += i4.w * p4.w;
        rII.x += i4.x * i4.x; rII.y += i4.y * i4.y; rII.z += i4.z * i4.z; rII.w += i4.w * i4.w;
    }

    const int eb = w * CS;
    const int k1 = lane * 4 + 1;
    const int sIdx0 = eb + PID(k1);
    const int sIdx1 = eb + PID(k1 + 1);
    const int sIdx2 = eb + PID(k1 + 2);
    const int sIdx3 = eb + PID(k1 + 3);

    for (int y = y0; y < y0 + SEG; ++y) {
        int ya = y + RAD;
        if (ya < HH) {
            float4 i4 = I4[(size_t)ya * 256 + tid];
            float4 p4 = P4[(size_t)ya * 256 + tid];
            rI.x  += i4.x;        rI.y  += i4.y;        rI.z  += i4.z;        rI.w  += i4.w;
            rP.x  += p4.x;        rP.y  += p4.y;        rP.z  += p4.z;        rP.w  += p4.w;
            rIp.x += i4.x * p4.x; rIp.y += i4.y * p4.y; rIp.z += i4.z * p4.z; rIp.w += i4.w * p4.w;
            rII.x += i4.x * i4.x; rII.y += i4.y * i4.y; rII.z += i4.z * i4.z; rII.w += i4.w * i4.w;
        }

        const int buf = y & 1;
        float* __restrict__ E0 = sE[buf][0];
        float* __restrict__ E1 = sE[buf][1];
        float* __restrict__ E2 = sE[buf][2];
        float* __restrict__ E3 = sE[buf][3];

        float4 pI, pP, pIp, pII;
        pI.x  = rI.x;  pI.y  = pI.x  + rI.y;  pI.z  = pI.y  + rI.z;  pI.w  = pI.z  + rI.w;
        pP.x  = rP.x;  pP.y  = pP.x  + rP.y;  pP.z  = pP.y  + rP.z;  pP.w  = pP.z  + rP.w;
        pIp.x = rIp.x; pIp.y = pIp.x + rIp.y; pIp.z = pIp.y + rIp.z; pIp.w = pIp.z + rIp.w;
        pII.x = rII.x; pII.y = pII.x + rII.y; pII.z = pII.y + rII.z; pII.w = pII.z + rII.w;

        float s0 = pI.w, s1 = pP.w, s2 = pIp.w, s3 = pII.w;
        float i0 = s0, i1 = s1, i2 = s2, i3 = s3;
        WSCAN(i0); WSCAN(i1); WSCAN(i2); WSCAN(i3);
        float x0 = i0 - s0, x1 = i1 - s1, x2 = i2 - s2, x3 = i3 - s3;

        if (lane == 0) { E0[eb] = 0.f; E1[eb] = 0.f; E2[eb] = 0.f; E3[eb] = 0.f; }
        E0[sIdx0] = x0 + pI.x;  E0[sIdx1] = x0 + pI.y;  E0[sIdx2] = x0 + pI.z;  E0[sIdx3] = x0 + pI.w;
        E1[sIdx0] = x1 + pP.x;  E1[sIdx1] = x1 + pP.y;  E1[sIdx2] = x1 + pP.z;  E1[sIdx3] = x1 + pP.w;
        E2[sIdx0] = x2 + pIp.x; E2[sIdx1] = x2 + pIp.y; E2[sIdx2] = x2 + pIp.z; E2[sIdx3] = x2 + pIp.w;
        E3[sIdx0] = x3 + pII.x; E3[sIdx1] = x3 + pII.y; E3[sIdx2] = x3 + pII.z; E3[sIdx3] = x3 + pII.w;

        __syncthreads();

        float cnty = (float)(min(y + RAD + 1, HH) - max(y - RAD, 0));
        float invy = __fdividef(1.0f, cnty);       // ONE MUFU per row
        H2x4 hv;
#pragma unroll
        for (int j = 0; j < 4; ++j) {
            float u0 = E0[aHi[j]] - E0[aLo[j]] + E0[aT[j]];
            float u1 = E1[aHi[j]] - E1[aLo[j]] + E1[aT[j]];
            float u2 = E2[aHi[j]] - E2[aLo[j]] + E2[aT[j]];
            float u3 = E3[aHi[j]] - E3[aLo[j]] + E3[aT[j]];
            float inv = invx[j] * invy;
            float mI  = u0 * inv;
            float mP  = u1 * inv;
            float mIp = u2 * inv;
            float mII = u3 * inv;
            float a = __fdividef(mIp - mI * mP, (mII - mI * mI) + EPS);
            float b = mP - a * mI;
            hv.v[j] = __floats2half2_rn(a, b);
        }
        AB[(size_t)y * 256 + tid] = hv;

        int yr = y - RAD;
        if (yr >= 0) {
            float4 i4 = I4[(size_t)yr * 256 + tid];
            float4 p4 = P4[(size_t)yr * 256 + tid];
            rI.x  -= i4.x;        rI.y  -= i4.y;        rI.z  -= i4.z;        rI.w  -= i4.w;
            rP.x  -= p4.x;        rP.y  -= p4.y;        rP.z  -= p4.z;        rP.w  -= p4.w;
            rIp.x -= i4.x * p4.x; rIp.y -= i4.y * p4.y; rIp.z -= i4.z * p4.z; rIp.w -= i4.w * p4.w;
            rII.x -= i4.x * i4.x; rII.y -= i4.y * i4.y; rII.z -= i4.z * i4.z; rII.w -= i4.w * i4.w;
        }
    }
}

// ---------------------------------------------------------------------------
// Stage 2: a,b (half2) -> box means -> out = mean_a * I + mean_b
// ---------------------------------------------------------------------------
__global__ __launch_bounds__(NTH) void k_stage2(const float* __restrict__ I,
                                                float* __restrict__ out) {
    __shared__ float sE[2][2][ESZ];

    const int tid  = threadIdx.x;
    const int lane = tid & 31;
    const int w    = tid >> 5;
    const int img  = blockIdx.y;
    const int y0   = blockIdx.x * SEG;
    const size_t b4 = (size_t)img * HH * 256;

    const H2x4* __restrict__ AB = g_ab + b4;
    const float4* __restrict__ I4 = (const float4*)I + b4;
    float4* __restrict__ O4 = (float4*)out + b4;

    const int c0 = tid * 4;

    int aLo[4], aHi[4], aT[4];
    float invx[4];
#pragma unroll
    for (int j = 0; j < 4; ++j) {
        int c   = c0 + j;
        int lo  = max(c - RAD, 0);
        int hi1 = min(c + RAD, WW - 1);
        int ca  = lo >> 7;
        int cb  = hi1 >> 7;
        aLo[j]  = ca * CS + PID(lo & 127);
        aHi[j]  = cb * CS + PID((hi1 & 127) + 1);
        aT[j]   = ca * CS + ((cb > ca) ? PID(128) : 0);
        invx[j] = 1.0f / (float)(hi1 + 1 - lo);
    }

    float rA[4] = {0.f, 0.f, 0.f, 0.f};
    float rB[4] = {0.f, 0.f, 0.f, 0.f};

    const int ys = max(0, y0 - RAD);
    const int ye = min(HH, y0 + RAD);
#pragma unroll 4
    for (int yy = ys; yy < ye; ++yy) {
        H2x4 h = AB[(size_t)yy * 256 + tid];
#pragma unroll
        for (int j = 0; j < 4; ++j) {
            float2 f = __half22float2(h.v[j]);
            rA[j] += f.x;
            rB[j] += f.y;
        }
    }

    const int eb = w * CS;
    const int k1 = lane * 4 + 1;
    const int sIdx0 = eb + PID(k1);
    const int sIdx1 = eb + PID(k1 + 1);
    const int sIdx2 = eb + PID(k1 + 2);
    const int sIdx3 = eb + PID(k1 + 3);

    for (int y = y0; y < y0 + SEG; ++y) {
        int ya = y + RAD;
        if (ya < HH) {
            H2x4 h = AB[(size_t)ya * 256 + tid];
#pragma unroll
            for (int j = 0; j < 4; ++j) {
                float2 f = __half22float2(h.v[j]);
                rA[j] += f.x;
                rB[j] += f.y;
            }
        }

        const int buf = y & 1;
        float* __restrict__ E0 = sE[buf][0];
        float* __restrict__ E1 = sE[buf][1];

        float4 pA, pB;
        pA.x = rA[0]; pA.y = pA.x + rA[1]; pA.z = pA.y + rA[2]; pA.w = pA.z + rA[3];
        pB.x = rB[0]; pB.y = pB.x + rB[1]; pB.z = pB.y + rB[2]; pB.w = pB.z + rB[3];

        float s0 = pA.w, s1 = pB.w;
        float i0 = s0, i1 = s1;
        WSCAN(i0); WSCAN(i1);
        float x0 = i0 - s0, x1 = i1 - s1;

        if (lane == 0) { E0[eb] = 0.f; E1[eb] = 0.f; }
        E0[sIdx0] = x0 + pA.x; E0[sIdx1] = x0 + pA.y; E0[sIdx2] = x0 + pA.z; E0[sIdx3] = x0 + pA.w;
        E1[sIdx0] = x1 + pB.x; E1[sIdx1] = x1 + pB.y; E1[sIdx2] = x1 + pB.z; E1[sIdx3] = x1 + pB.w;

        __syncthreads();

        float cnty = (float)(min(y + RAD + 1, HH) - max(y - RAD, 0));
        float invy = __fdividef(1.0f, cnty);       // ONE MUFU per row
        float4 i4 = I4[(size_t)y * 256 + tid];
        const float* ip = &i4.x;
        float4 ov;
        float* op = &ov.x;
#pragma unroll
        for (int j = 0; j < 4; ++j) {
            float sa = E0[aHi[j]] - E0[aLo[j]] + E0[aT[j]];
            float sb = E1[aHi[j]] - E1[aLo[j]] + E1[aT[j]];
            float inv = invx[j] * invy;
            op[j] = (sa * inv) * ip[j] + (sb * inv);
        }
        O4[(size_t)y * 256 + tid] = ov;

        int yr = y - RAD;
        if (yr >= 0) {
            H2x4 h = AB[(size_t)yr * 256 + tid];
#pragma unroll
            for (int j = 0; j < 4; ++j) {
                float2 f = __half22float2(h.v[j]);
                rA[j] -= f.x;
                rB[j] -= f.y;
            }
        }
    }
}

extern "C" void kernel_launch(void* const* d_in, const int* in_sizes, int n_in,
                              void* d_out, int out_size) {
    const float* I = (const float*)d_in[0];
    const float* P = (const float*)d_in[1];
    float* out = (float*)d_out;

    dim3 g(HH / SEG, NIMG);
    k_stage1<<<g, NTH>>>(I, P);
    k_stage2<<<g, NTH>>>(I, out);
}